// round 9
// baseline (speedup 1.0000x reference)
#include <cuda_runtime.h>
#include <stdint.h>

#define BB   256          // batch (images / segments)
#define DD   512          // embedding dim
#define HWQ  256          // H*W spatial positions
#define NT   256          // threads per block
#define DH   256          // d-half size (DD/2)
#define DH4  64           // float4s per half-vector

// ---------------------------------------------------------------------------
// 1024 uniform blocks x 256 threads, single wave at 8 blocks/SM.
//   bid in [0,512)    : img item (j = bid>>1, h = bid&1)
//       reduce d-rows [256h,256h+256) of Z_img[j]  (256 KiB contiguous read)
//       STG-write M_img[i, j, 256h:+256) for all i (256 x 1 KiB, stride 512 KiB)
//   bid in [512,1024) : snd item (b = (bid-512)>>1, h)
//       scan splits in-smem (dtype-robust), reduce cols [256h,+256) of
//       segment b (128 KiB read), STG-write M_snd[b, :, 256h:+256)
// All writes are st.global.cs (streaming); warp stores 512 B contiguous per
// instruction with 8 independent rows in flight -> no per-op service cost.
// Output layout: [ M_img (B,B,D) | M_snd (B,B,D) ].
// ---------------------------------------------------------------------------
__global__ __launch_bounds__(NT, 8)
void fused_meanpool_bcast(const float* __restrict__ Zimg,
                          const float* __restrict__ Zsnd,
                          const int*   __restrict__ splits,
                          float*       __restrict__ out,
                          long long T) {
    __shared__ long long s_scan[BB];                   // 2 KiB (snd only)
    __shared__ float4    s_part[4][DH4];               // 4 KiB (snd only)
    __shared__ __align__(16) float s_half[DH];         // 1 KiB half-vector

    const int t    = threadIdx.x;
    const int wid  = t >> 5;
    const int lane = t & 31;
    const size_t NIMG = (size_t)BB * BB * DD;          // floats in M_img

    if (blockIdx.x < 512) {
        // =================== IMG ITEM ===================
        const int j = blockIdx.x >> 1;
        const int h = blockIdx.x & 1;

        // rows [256h, 256h+256): contiguous 256 KiB slab
        const float4* p = reinterpret_cast<const float4*>(
            Zimg + ((size_t)j * DD + (size_t)h * DH) * HWQ);

        // 8 warps x 32 rows each; per row: 64 float4, 2 per lane
        for (int k = 0; k < 32; ++k) {
            int lr = wid * 32 + k;                     // local d-row 0..255
            float4 a = __ldcs(&p[(size_t)lr * 64 + lane]);
            float4 b = __ldcs(&p[(size_t)lr * 64 + 32 + lane]);
            float s = (a.x + a.y) + (a.z + a.w) + (b.x + b.y) + (b.z + b.w);
#pragma unroll
            for (int o = 16; o > 0; o >>= 1)
                s += __shfl_down_sync(0xffffffffu, s, o);
            if (lane == 0)
                s_half[lr] = s * (1.0f / (float)HWQ);
        }
        __syncthreads();

        // STG-write: each thread owns float4 column (t & 63); 4 cols-groups.
        // 256 threads = 4 row-slices x 64 cols; 8 rows in flight chip-wide.
        {
            const int col   = t & (DH4 - 1);           // 0..63
            const int slice = t >> 6;                  // 0..3
            float4 v = reinterpret_cast<const float4*>(s_half)[col];
            float4* dst0 = reinterpret_cast<float4*>(
                out + (size_t)j * DD + (size_t)h * DH) + col;
            const size_t STR4 = (size_t)BB * DD / 4;   // float4 stride = row i
#pragma unroll 8
            for (int i = slice; i < BB; i += 4)
                __stcs(dst0 + (size_t)i * STR4, v);
        }

    } else {
        // =================== SND ITEM ===================
        const int id = blockIdx.x - 512;
        const int b  = id >> 1;
        const int h  = id & 1;

        // --- in-block inclusive scan of splits (dtype-robust) ---
        s_scan[t] = (long long)splits[t];
        __syncthreads();
#pragma unroll
        for (int off = 1; off < BB; off <<= 1) {
            long long v = (t >= off) ? s_scan[t - off] : 0LL;
            __syncthreads();
            s_scan[t] += v;
            __syncthreads();
        }
        if (s_scan[BB - 1] != T) {
            const long long* p64 = (const long long*)splits;
            __syncthreads();
            s_scan[t] = p64[t];
            __syncthreads();
#pragma unroll
            for (int off = 1; off < BB; off <<= 1) {
                long long v = (t >= off) ? s_scan[t - off] : 0LL;
                __syncthreads();
                s_scan[t] += v;
                __syncthreads();
            }
        }
        __syncthreads();
        const long long start = (b == 0) ? 0LL : s_scan[b - 1];
        const long long len   = s_scan[b] - start;

        // --- reduce cols [64h..64h+64) float4 over segment rows ---
        const int col   = t & (DH4 - 1);               // 0..63
        const int slice = t >> 6;                      // 0..3
        long long r0 = start + (len * slice)       / 4;
        long long r1 = start + (len * (slice + 1)) / 4;

        const float4* p = reinterpret_cast<const float4*>(Zsnd);
        float4 acc = make_float4(0.f, 0.f, 0.f, 0.f);
        for (long long r = r0; r < r1; ++r) {
            float4 v = __ldcs(&p[r * (DD / 4) + h * DH4 + col]);
            acc.x += v.x; acc.y += v.y; acc.z += v.z; acc.w += v.w;
        }
        s_part[slice][col] = acc;
        __syncthreads();

        float4 v;
        {
            float4 a0 = s_part[0][col], a1 = s_part[1][col],
                   a2 = s_part[2][col], a3 = s_part[3][col];
            float inv = (len > 0) ? (1.0f / (float)len) : 0.0f;
            v.x = (a0.x + a1.x + a2.x + a3.x) * inv;
            v.y = (a0.y + a1.y + a2.y + a3.y) * inv;
            v.z = (a0.z + a1.z + a2.z + a3.z) * inv;
            v.w = (a0.w + a1.w + a2.w + a3.w) * inv;
        }
        // every thread already holds its column's value -> no extra sync

        // STG-write: 256 rows x 1 KiB at 2 KiB stride
        {
            float4* dst0 = reinterpret_cast<float4*>(
                out + NIMG + (size_t)b * BB * DD + (size_t)h * DH) + col;
            const size_t STR4 = (size_t)DD / 4;        // float4 stride = row i
#pragma unroll 8
            for (int i = slice; i < BB; i += 4)
                __stcs(dst0 + (size_t)i * STR4, v);
        }
    }
}

// ---------------------------------------------------------------------------
extern "C" void kernel_launch(void* const* d_in, const int* in_sizes, int n_in,
                              void* d_out, int out_size) {
    // Identify inputs by element count:
    //   Z_img: 33,554,432   Z_snd: 16,777,216   splits: 256
    const float* Zimg   = nullptr;
    const float* Zsnd   = nullptr;
    const int*   splits = nullptr;
    long long    Tsnd   = 0;

    for (int i = 0; i < n_in; ++i) {
        if (in_sizes[i] == BB) {
            splits = (const int*)d_in[i];
        } else if (in_sizes[i] == BB * DD * HWQ) {
            Zimg = (const float*)d_in[i];
        } else {
            Zsnd = (const float*)d_in[i];
            Tsnd = (long long)(in_sizes[i] / DD);
        }
    }
    (void)out_size;

    fused_meanpool_bcast<<<1024, NT>>>(Zimg, Zsnd, splits,
                                       (float*)d_out, Tsnd);
}